// round 2
// baseline (speedup 1.0000x reference)
#include <cuda_runtime.h>
#include <cuda_bf16.h>
#include <cstdint>

#define BATCH 128
#define SEQ   512
#define HID   1024
#define H2    2048
#define EMB   512
#define VOCAB 32000
#define KG    3584          /* 2048 ctx + 512 emb + 1024 h */
#define NG    4096
#define SPLIT 4             /* attention seq splits */
#define LDS_PAD 40          /* 80B row stride -> conflict-free ldmatrix */
#define STG_ELEMS (4 * 128 * LDS_PAD)   /* Ah|Al|Bh|Bl per stage (bf16) */

__device__ float g_ctx[SPLIT * BATCH * H2];        // unnormalized partial contexts
__device__ float g_z[SPLIT * BATCH];               // partial softmax denominators
__device__ float g_gates_part[SPLIT * BATCH * NG]; // split-K gate partials

// ---------------------------------------------------------------------------
// attention: partial pass over encoder_states, no max-shift (energies bounded).
// grid (BATCH, SPLIT); each CTA handles 128 s-values; 8 warps stride-8.
// Warp-private 2048-wide register accumulators, merged via smem atomics,
// written non-atomically to this CTA's private partial-context slot.
// ---------------------------------------------------------------------------
__global__ __launch_bounds__(256) void attn_kernel(
    const float* __restrict__ enc,
    const float* __restrict__ hidden,
    const float* __restrict__ W_e,
    const float* __restrict__ b_e)
{
    __shared__ float s_w2[H2];
    __shared__ float s_acc[H2];
    __shared__ float s_red[8];
    __shared__ float s_z[8];
    __shared__ float s_hb;

    int b = blockIdx.x, split = blockIdx.y, t = threadIdx.x;
    int warp = t >> 5, lane = t & 31;

    for (int j = t; j < H2; j += 256) { s_w2[j] = W_e[HID + j]; s_acc[j] = 0.f; }

    // hb = hidden[b] . W_e[0:HID] + b_e
    float p = 0.f;
    for (int j = t; j < HID; j += 256) p += hidden[b * HID + j] * W_e[j];
    #pragma unroll
    for (int o = 16; o > 0; o >>= 1) p += __shfl_xor_sync(0xffffffffu, p, o);
    if (lane == 0) s_red[warp] = p;
    __syncthreads();
    if (t == 0) {
        float s = 0.f;
        #pragma unroll
        for (int i = 0; i < 8; i++) s += s_red[i];
        s_hb = s + b_e[0];
    }
    __syncthreads();
    float hb = s_hb;

    float4 acc[16];
    #pragma unroll
    for (int i = 0; i < 16; i++) acc[i] = make_float4(0.f, 0.f, 0.f, 0.f);
    float Zw = 0.f;
    const float4* w2v = (const float4*)s_w2;

    int s0 = split * (SEQ / SPLIT), s1 = s0 + (SEQ / SPLIT);
    for (int s = s0 + warp; s < s1; s += 8) {
        const float4* row = (const float4*)(enc + ((size_t)s * BATCH + b) * H2);
        float4 v[16];
        float pr = 0.f;
        #pragma unroll
        for (int i = 0; i < 16; i++) {
            v[i] = row[lane + 32 * i];
            float4 w = w2v[lane + 32 * i];
            pr += v[i].x * w.x + v[i].y * w.y + v[i].z * w.z + v[i].w * w.w;
        }
        #pragma unroll
        for (int o = 16; o > 0; o >>= 1) pr += __shfl_xor_sync(0xffffffffu, pr, o);
        float wg = __expf(fmaxf(pr + hb, 0.f));   // relu then exp, no shift
        Zw += wg;
        #pragma unroll
        for (int i = 0; i < 16; i++) {
            acc[i].x += wg * v[i].x;
            acc[i].y += wg * v[i].y;
            acc[i].z += wg * v[i].z;
            acc[i].w += wg * v[i].w;
        }
    }

    #pragma unroll
    for (int i = 0; i < 16; i++) {
        int c = 4 * (lane + 32 * i);
        atomicAdd(&s_acc[c + 0], acc[i].x);
        atomicAdd(&s_acc[c + 1], acc[i].y);
        atomicAdd(&s_acc[c + 2], acc[i].z);
        atomicAdd(&s_acc[c + 3], acc[i].w);
    }
    if (lane == 0) s_z[warp] = Zw;
    __syncthreads();

    float* dst = g_ctx + ((size_t)split * BATCH + b) * H2;
    for (int j = t; j < H2; j += 256) dst[j] = s_acc[j];
    if (t == 0) {
        float z = 0.f;
        #pragma unroll
        for (int i = 0; i < 8; i++) z += s_z[i];
        g_z[split * BATCH + b] = z;
    }
}

// ---------------------------------------------------------------------------
// bf16x3 split GEMM, 2-stage smem pipeline:
//   C[128, N] = A[128, K] @ B[N, K]^T   (fp32 in/out)
// mode 0 (gates): A assembled on the fly = [sum(ctx partials)/Z | emb | hidden],
//                 B piecewise = W_ih then W_hh, C = split-K partial buffer.
// mode 1 (fc):    A = h_new, B = W_fc, C = predictions + bias.
// ---------------------------------------------------------------------------
__device__ __forceinline__ void ldm_x4(uint32_t* r, const __nv_bfloat16* p) {
    uint32_t a = (uint32_t)__cvta_generic_to_shared(p);
    asm volatile("ldmatrix.sync.aligned.m8n8.x4.shared.b16 {%0,%1,%2,%3}, [%4];\n"
                 : "=r"(r[0]), "=r"(r[1]), "=r"(r[2]), "=r"(r[3]) : "r"(a));
}
__device__ __forceinline__ void ldm_x2(uint32_t* r, const __nv_bfloat16* p) {
    uint32_t a = (uint32_t)__cvta_generic_to_shared(p);
    asm volatile("ldmatrix.sync.aligned.m8n8.x2.shared.b16 {%0,%1}, [%2];\n"
                 : "=r"(r[0]), "=r"(r[1]) : "r"(a));
}
__device__ __forceinline__ void mma_bf16(float* d, const uint32_t* a, const uint32_t* b) {
    asm volatile("mma.sync.aligned.m16n8k16.row.col.f32.bf16.bf16.f32 "
                 "{%0,%1,%2,%3}, {%4,%5,%6,%7}, {%8,%9}, {%0,%1,%2,%3};\n"
                 : "+f"(d[0]), "+f"(d[1]), "+f"(d[2]), "+f"(d[3])
                 : "r"(a[0]), "r"(a[1]), "r"(a[2]), "r"(a[3]), "r"(b[0]), "r"(b[1]));
}

extern __shared__ __nv_bfloat16 smb[];

__global__ __launch_bounds__(256) void gemm_kernel(
    int mode,
    const int*   __restrict__ x,
    const float* __restrict__ emb_table,
    const float* __restrict__ hidden,
    const float* __restrict__ W_ih, const float* __restrict__ W_hh,
    const float* __restrict__ W_fc, const float* __restrict__ b_fc,
    const float* __restrict__ h_new, float* __restrict__ pred)
{
    __shared__ int   s_tok[BATCH];
    __shared__ float s_invZ[BATCH];

    int t = threadIdx.x, warp = t >> 5, lane = t & 31;
    int ntile = blockIdx.x;

    if (mode == 0 && t < BATCH) {
        s_tok[t] = x[t];
        float z = 0.f;
        #pragma unroll
        for (int sp = 0; sp < SPLIT; sp++) z += g_z[sp * BATCH + t];
        s_invZ[t] = 1.f / z;
    }
    __syncthreads();

    const float *B1, *B2, *bias;
    int k1, ldb1, ldb2, Ktot;
    if (mode == 0) {
        Ktot = KG;  B1 = W_ih; k1 = H2 + EMB; ldb1 = H2 + EMB; B2 = W_hh; ldb2 = HID;
        bias = nullptr;
    } else {
        Ktot = HID; B1 = W_fc; k1 = HID;      ldb1 = HID;      B2 = W_fc; ldb2 = HID;
        bias = b_fc;
    }

    int nch = Ktot >> 5;
    int per = nch / gridDim.y;
    int c0 = blockIdx.y * per, c1 = c0 + per;

    float acc[4][4][4];
    #pragma unroll
    for (int mi = 0; mi < 4; mi++)
        #pragma unroll
        for (int ni = 0; ni < 4; ni++)
            #pragma unroll
            for (int q = 0; q < 4; q++) acc[mi][ni][q] = 0.f;

    int rowL[4], kqL[4];
    #pragma unroll
    for (int j = 0; j < 4; j++) { int idx = t + j * 256; rowL[j] = idx >> 3; kqL[j] = idx & 7; }

    float4 pa[4], pb[4];

    // ---- chunk loader into registers ----
    auto load_chunk = [&](int ch) {
        #pragma unroll
        for (int j = 0; j < 4; j++) {
            int k = (ch << 5) + kqL[j] * 4;
            int row = rowL[j];
            if (mode == 0) {
                if (k < H2) {
                    const float* c = g_ctx + (size_t)row * H2 + k;
                    float4 a0 = *(const float4*)(c);
                    float4 a1 = *(const float4*)(c + (size_t)BATCH * H2);
                    float4 a2 = *(const float4*)(c + 2 * (size_t)BATCH * H2);
                    float4 a3 = *(const float4*)(c + 3 * (size_t)BATCH * H2);
                    float iz = s_invZ[row];
                    pa[j] = make_float4((a0.x + a1.x + a2.x + a3.x) * iz,
                                        (a0.y + a1.y + a2.y + a3.y) * iz,
                                        (a0.z + a1.z + a2.z + a3.z) * iz,
                                        (a0.w + a1.w + a2.w + a3.w) * iz);
                } else if (k < H2 + EMB) {
                    pa[j] = *(const float4*)(emb_table + (size_t)s_tok[row] * EMB + (k - H2));
                } else {
                    pa[j] = *(const float4*)(hidden + (size_t)row * HID + (k - H2 - EMB));
                }
            } else {
                pa[j] = *(const float4*)(h_new + (size_t)row * HID + k);
            }
            int rg = ntile * 128 + row;
            const float* s = (k < k1) ? (B1 + (size_t)rg * ldb1 + k)
                                      : (B2 + (size_t)rg * ldb2 + (k - k1));
            pb[j] = *(const float4*)s;
        }
    };

    // ---- convert + store staged chunk into smem stage ----
    auto store_stage = [&](int stg) {
        __nv_bfloat16* Ah = smb + stg * STG_ELEMS;
        __nv_bfloat16* Al = Ah + 5120;
        __nv_bfloat16* Bh = Ah + 10240;
        __nv_bfloat16* Bl = Ah + 15360;
        #pragma unroll
        for (int j = 0; j < 4; j++) {
            int off = rowL[j] * LDS_PAD + kqL[j] * 4;
            float av[4] = { pa[j].x, pa[j].y, pa[j].z, pa[j].w };
            float bv[4] = { pb[j].x, pb[j].y, pb[j].z, pb[j].w };
            __nv_bfloat16 h[4], l[4], bh[4], bl[4];
            #pragma unroll
            for (int c = 0; c < 4; c++) {
                h[c]  = __float2bfloat16(av[c]);
                l[c]  = __float2bfloat16(av[c] - __bfloat162float(h[c]));
                bh[c] = __float2bfloat16(bv[c]);
                bl[c] = __float2bfloat16(bv[c] - __bfloat162float(bh[c]));
            }
            *(__nv_bfloat162*)(Ah + off)     = __halves2bfloat162(h[0],  h[1]);
            *(__nv_bfloat162*)(Ah + off + 2) = __halves2bfloat162(h[2],  h[3]);
            *(__nv_bfloat162*)(Al + off)     = __halves2bfloat162(l[0],  l[1]);
            *(__nv_bfloat162*)(Al + off + 2) = __halves2bfloat162(l[2],  l[3]);
            *(__nv_bfloat162*)(Bh + off)     = __halves2bfloat162(bh[0], bh[1]);
            *(__nv_bfloat162*)(Bh + off + 2) = __halves2bfloat162(bh[2], bh[3]);
            *(__nv_bfloat162*)(Bl + off)     = __halves2bfloat162(bl[0], bl[1]);
            *(__nv_bfloat162*)(Bl + off + 2) = __halves2bfloat162(bl[2], bl[3]);
        }
    };

    int mw = (warp >> 2) * 64, nw = (warp & 3) * 32;

    // ---- mma over one smem stage ----
    auto mma_stage = [&](int stg) {
        __nv_bfloat16* Ah = smb + stg * STG_ELEMS;
        __nv_bfloat16* Al = Ah + 5120;
        __nv_bfloat16* Bh = Ah + 10240;
        __nv_bfloat16* Bl = Ah + 15360;
        #pragma unroll
        for (int ks = 0; ks < 2; ks++) {
            uint32_t ah[4][4], al[4][4], bhf[4][2], blf[4][2];
            int ar = mw + (lane & 15);
            int ac = ks * 16 + ((lane >> 4) << 3);
            #pragma unroll
            for (int mi = 0; mi < 4; mi++) {
                ldm_x4(ah[mi], &Ah[(ar + mi * 16) * LDS_PAD + ac]);
                ldm_x4(al[mi], &Al[(ar + mi * 16) * LDS_PAD + ac]);
            }
            int br = nw + (lane & 7);
            int bc = ks * 16 + ((lane >> 3) & 1) * 8;
            #pragma unroll
            for (int ni = 0; ni < 4; ni++) {
                ldm_x2(bhf[ni], &Bh[(br + ni * 8) * LDS_PAD + bc]);
                ldm_x2(blf[ni], &Bl[(br + ni * 8) * LDS_PAD + bc]);
            }
            #pragma unroll
            for (int mi = 0; mi < 4; mi++)
                #pragma unroll
                for (int ni = 0; ni < 4; ni++) mma_bf16(acc[mi][ni], ah[mi], bhf[ni]);
            #pragma unroll
            for (int mi = 0; mi < 4; mi++)
                #pragma unroll
                for (int ni = 0; ni < 4; ni++) mma_bf16(acc[mi][ni], al[mi], bhf[ni]);
            #pragma unroll
            for (int mi = 0; mi < 4; mi++)
                #pragma unroll
                for (int ni = 0; ni < 4; ni++) mma_bf16(acc[mi][ni], ah[mi], blf[ni]);
        }
    };

    // ---- 2-stage pipeline ----
    load_chunk(c0);
    store_stage(0);
    if (c0 + 1 < c1) load_chunk(c0 + 1);
    __syncthreads();
    for (int ch = c0; ch < c1; ++ch) {
        int cur = (ch - c0) & 1;
        if (ch + 1 < c1) {
            store_stage(cur ^ 1);
            if (ch + 2 < c1) load_chunk(ch + 2);
        }
        mma_stage(cur);
        __syncthreads();
    }

    // ---- epilogue ----
    int r0 = mw + (lane >> 2);
    int cb = nw + (lane & 3) * 2;
    if (mode == 0) {
        float* Cp = g_gates_part + (size_t)blockIdx.y * BATCH * NG;
        #pragma unroll
        for (int mi = 0; mi < 4; mi++)
            #pragma unroll
            for (int ni = 0; ni < 4; ni++) {
                int ng0 = ntile * 128 + cb + ni * 8;
                int rA  = r0 + mi * 16;
                Cp[(size_t)rA * NG + ng0]           = acc[mi][ni][0];
                Cp[(size_t)rA * NG + ng0 + 1]       = acc[mi][ni][1];
                Cp[(size_t)(rA + 8) * NG + ng0]     = acc[mi][ni][2];
                Cp[(size_t)(rA + 8) * NG + ng0 + 1] = acc[mi][ni][3];
            }
    } else {
        #pragma unroll
        for (int mi = 0; mi < 4; mi++)
            #pragma unroll
            for (int ni = 0; ni < 4; ni++) {
                int ng0 = ntile * 128 + cb + ni * 8;
                int rA  = r0 + mi * 16;
                pred[(size_t)rA * VOCAB + ng0]           = acc[mi][ni][0] + bias[ng0];
                pred[(size_t)rA * VOCAB + ng0 + 1]       = acc[mi][ni][1] + bias[ng0 + 1];
                pred[(size_t)(rA + 8) * VOCAB + ng0]     = acc[mi][ni][2] + bias[ng0];
                pred[(size_t)(rA + 8) * VOCAB + ng0 + 1] = acc[mi][ni][3] + bias[ng0 + 1];
            }
    }
}

// ---------------------------------------------------------------------------
// LSTM pointwise: sum 4 split-K gate partials -> h_new, c_new
// ---------------------------------------------------------------------------
__device__ __forceinline__ float sigmf(float x) { return 1.f / (1.f + __expf(-x)); }
__device__ __forceinline__ float tanhfast(float x) { return 1.f - 2.f / (1.f + __expf(2.f * x)); }

__global__ __launch_bounds__(256) void lstm_kernel(
    const float* __restrict__ b_ih,
    const float* __restrict__ b_hh,
    const float* __restrict__ cell,
    float* __restrict__ h_out,
    float* __restrict__ c_out)
{
    int idx = blockIdx.x * 256 + threadIdx.x;     // 128*1024 threads
    int b = idx >> 10, j = idx & 1023;
    const float* g = g_gates_part + (size_t)b * NG;
    float gs[4];
    #pragma unroll
    for (int gi = 0; gi < 4; gi++) {
        int col = gi * HID + j;
        float v = b_ih[col] + b_hh[col];
        #pragma unroll
        for (int y = 0; y < SPLIT; y++) v += g[(size_t)y * BATCH * NG + col];
        gs[gi] = v;
    }
    float ig = sigmf(gs[0]);
    float fg = sigmf(gs[1]);
    float gg = tanhfast(gs[2]);
    float og = sigmf(gs[3]);
    float c = fg * cell[idx] + ig * gg;
    float h = og * tanhfast(c);
    c_out[idx] = c;
    h_out[idx] = h;
}

// ---------------------------------------------------------------------------
extern "C" void kernel_launch(void* const* d_in, const int* in_sizes, int n_in,
                              void* d_out, int out_size)
{
    const int*   x      = (const int*)d_in[0];
    const float* enc    = (const float*)d_in[1];
    const float* hidden = (const float*)d_in[2];
    const float* cell   = (const float*)d_in[3];
    const float* emb    = (const float*)d_in[4];
    const float* W_e    = (const float*)d_in[5];
    const float* b_e    = (const float*)d_in[6];
    const float* W_ih   = (const float*)d_in[7];
    const float* W_hh   = (const float*)d_in[8];
    const float* b_ih   = (const float*)d_in[9];
    const float* b_hh   = (const float*)d_in[10];
    const float* W_fc   = (const float*)d_in[11];
    const float* b_fc   = (const float*)d_in[12];

    float* out   = (float*)d_out;
    float* h_out = out + (size_t)BATCH * VOCAB;
    float* c_out = h_out + BATCH * HID;

    static bool attr_set = false;
    if (!attr_set) {
        cudaFuncSetAttribute(gemm_kernel,
                             cudaFuncAttributeMaxDynamicSharedMemorySize,
                             2 * STG_ELEMS * (int)sizeof(__nv_bfloat16));
        attr_set = true;
    }
    size_t smem = 2 * STG_ELEMS * sizeof(__nv_bfloat16);

    attn_kernel<<<dim3(BATCH, SPLIT), 256>>>(enc, hidden, W_e, b_e);
    gemm_kernel<<<dim3(NG / 128, SPLIT), 256, smem>>>(
        0, x, emb, hidden, W_ih, W_hh, W_fc, b_fc, h_out, out);
    lstm_kernel<<<(BATCH * HID) / 256, 256>>>(b_ih, b_hh, cell, h_out, c_out);
    gemm_kernel<<<dim3(VOCAB / 128, 1), 256, smem>>>(
        1, x, emb, hidden, W_ih, W_hh, W_fc, b_fc, h_out, out);
}

// round 4
// speedup vs baseline: 1.1624x; 1.1624x over previous
#include <cuda_runtime.h>
#include <cuda_bf16.h>
#include <cstdint>

#define BATCH 128
#define SEQ   512
#define HID   1024
#define H2    2048
#define EMB   512
#define VOCAB 32000
#define KG    3584          /* 2048 ctx + 512 emb + 1024 hidden */
#define NG    4096
#define K1G   (H2 + EMB)    /* 2560 = W_ih K extent */
#define GSPLIT 4            /* split-K for gate GEMM */
#define LDS_PAD 40          /* 80B bf16 row stride -> conflict-free ldmatrix */
#define STG_ELEMS (4 * 128 * LDS_PAD)   /* Ah|Al|Bh|Bl per stage */
#define GEMM_SMEM (2 * STG_ELEMS * (int)sizeof(__nv_bfloat16))

__device__ float g_ctx[BATCH * H2];                 // normalized context
__device__ float g_gates_part[GSPLIT * BATCH * NG]; // split-K gate partials

// ===========================================================================
// attention: 1 CTA / batch elem, single streaming pass, no max-shift
// (energies relu-bounded ~6 -> exp safe). Register double-buffered rows
// keep 16 LDG.128 in flight across the dot/exp/acc dependency chain.
// ===========================================================================
__device__ __forceinline__ void attn_step(
    const float4* __restrict__ w2v, const float4 v[16],
    float hb, float& Zw, float4 acc[16])
{
    float pr = 0.f;
    #pragma unroll
    for (int i = 0; i < 16; i++) {
        float4 w = w2v[i];
        pr += v[i].x * w.x + v[i].y * w.y + v[i].z * w.z + v[i].w * w.w;
    }
    #pragma unroll
    for (int o = 16; o > 0; o >>= 1) pr += __shfl_xor_sync(0xffffffffu, pr, o);
    float wg = __expf(fmaxf(pr + hb, 0.f));
    Zw += wg;
    #pragma unroll
    for (int i = 0; i < 16; i++) {
        acc[i].x += wg * v[i].x; acc[i].y += wg * v[i].y;
        acc[i].z += wg * v[i].z; acc[i].w += wg * v[i].w;
    }
}

__global__ __launch_bounds__(256) void attn_kernel(
    const float* __restrict__ enc, const float* __restrict__ hidden,
    const float* __restrict__ W_e, const float* __restrict__ b_e)
{
    __shared__ float s_w2[H2], s_acc[H2];
    __shared__ float s_red[8], s_z[8];
    __shared__ float s_hb, s_invZ;

    int b = blockIdx.x, t = threadIdx.x;
    int warp = t >> 5, lane = t & 31;

    for (int j = t; j < H2; j += 256) { s_w2[j] = W_e[HID + j]; s_acc[j] = 0.f; }

    float p = 0.f;
    for (int j = t; j < HID; j += 256) p += hidden[b * HID + j] * W_e[j];
    #pragma unroll
    for (int o = 16; o > 0; o >>= 1) p += __shfl_xor_sync(0xffffffffu, p, o);
    if (lane == 0) s_red[warp] = p;
    __syncthreads();
    if (t == 0) {
        float s = 0.f;
        #pragma unroll
        for (int i = 0; i < 8; i++) s += s_red[i];
        s_hb = s + b_e[0];
    }
    __syncthreads();
    float hb = s_hb;

    // per-thread lane-strided view of w2 (smem, conflict-free)
    const float4* w2v = ((const float4*)s_w2) + lane;
    // w2v[i] means element (lane + 32*i) -> build a register-friendly accessor
    // via explicit indexing below.

    float4 acc[16];
    #pragma unroll
    for (int i = 0; i < 16; i++) acc[i] = make_float4(0.f, 0.f, 0.f, 0.f);
    float Zw = 0.f;

    float4 va[16], vb[16];
    float4 w2r[16];
    #pragma unroll
    for (int i = 0; i < 16; i++) w2r[i] = w2v[32 * i];

    {
        const float4* row = (const float4*)(enc + ((size_t)warp * BATCH + b) * H2);
        #pragma unroll
        for (int i = 0; i < 16; i++) va[i] = row[lane + 32 * i];
    }

    for (int s = warp; s < SEQ; s += 16) {
        // prefetch s+8 while processing s
        {
            const float4* row = (const float4*)(enc + ((size_t)(s + 8) * BATCH + b) * H2);
            #pragma unroll
            for (int i = 0; i < 16; i++) vb[i] = row[lane + 32 * i];
        }
        attn_step(w2r, va, hb, Zw, acc);
        // prefetch s+16 while processing s+8
        if (s + 16 < SEQ) {
            const float4* row = (const float4*)(enc + ((size_t)(s + 16) * BATCH + b) * H2);
            #pragma unroll
            for (int i = 0; i < 16; i++) va[i] = row[lane + 32 * i];
        }
        attn_step(w2r, vb, hb, Zw, acc);
    }

    #pragma unroll
    for (int i = 0; i < 16; i++) {
        int c = 4 * (lane + 32 * i);
        atomicAdd(&s_acc[c + 0], acc[i].x);
        atomicAdd(&s_acc[c + 1], acc[i].y);
        atomicAdd(&s_acc[c + 2], acc[i].z);
        atomicAdd(&s_acc[c + 3], acc[i].w);
    }
    if (lane == 0) s_z[warp] = Zw;
    __syncthreads();
    if (t == 0) {
        float z = 0.f;
        #pragma unroll
        for (int i = 0; i < 8; i++) z += s_z[i];
        s_invZ = 1.f / z;
    }
    __syncthreads();
    float iz = s_invZ;
    float* dst = g_ctx + (size_t)b * H2;
    for (int j = t; j < H2; j += 256) dst[j] = s_acc[j] * iz;
}

// ===========================================================================
// bf16x3 split GEMM (mma.sync), double-buffered smem, 2 CTAs/SM:
//   C[128, 128-tile] = A[128,K] @ B[Ntile,K]^T   (fp32 in/out)
// mode 0: gates — A = [ctx | emb | hidden] on the fly, B = W_ih|W_hh,
//                 K split GSPLIT ways, C -> g_gates_part.
// mode 1: fc    — A = h_new, B = W_fc, C = pred + bias.
// ===========================================================================
__device__ __forceinline__ void ldm_x4(uint32_t* r, const __nv_bfloat16* p) {
    uint32_t a = (uint32_t)__cvta_generic_to_shared(p);
    asm volatile("ldmatrix.sync.aligned.m8n8.x4.shared.b16 {%0,%1,%2,%3}, [%4];\n"
                 : "=r"(r[0]), "=r"(r[1]), "=r"(r[2]), "=r"(r[3]) : "r"(a));
}
__device__ __forceinline__ void ldm_x2(uint32_t* r, const __nv_bfloat16* p) {
    uint32_t a = (uint32_t)__cvta_generic_to_shared(p);
    asm volatile("ldmatrix.sync.aligned.m8n8.x2.shared.b16 {%0,%1}, [%2];\n"
                 : "=r"(r[0]), "=r"(r[1]) : "r"(a));
}
__device__ __forceinline__ void mma_bf16(float* d, const uint32_t* a, const uint32_t* b) {
    asm volatile("mma.sync.aligned.m16n8k16.row.col.f32.bf16.bf16.f32 "
                 "{%0,%1,%2,%3}, {%4,%5,%6,%7}, {%8,%9}, {%0,%1,%2,%3};\n"
                 : "+f"(d[0]), "+f"(d[1]), "+f"(d[2]), "+f"(d[3])
                 : "r"(a[0]), "r"(a[1]), "r"(a[2]), "r"(a[3]), "r"(b[0]), "r"(b[1]));
}

extern __shared__ __nv_bfloat16 smb[];

__global__ __launch_bounds__(256, 2) void gemm_kernel(
    int mode,
    const int*   __restrict__ x,
    const float* __restrict__ emb_table,
    const float* __restrict__ hidden,
    const float* __restrict__ W_ih, const float* __restrict__ W_hh,
    const float* __restrict__ W_fc, const float* __restrict__ b_fc,
    const float* __restrict__ h_new, float* __restrict__ pred)
{
    __shared__ int   s_tok[BATCH];
    __shared__ float s_bias[128];

    int t = threadIdx.x, warp = t >> 5, lane = t & 31;
    int nt = blockIdx.x, split = blockIdx.y;

    if (mode == 0 && t < BATCH) s_tok[t] = x[t];
    if (mode == 1 && t < 128)   s_bias[t] = b_fc[nt * 128 + t];

    int Kbase, NC;
    if (mode == 0) { Kbase = split * (KG / GSPLIT); NC = (KG / GSPLIT) >> 5; }
    else           { Kbase = 0;                     NC = HID >> 5; }

    float acc[4][4][4];
    #pragma unroll
    for (int mi = 0; mi < 4; mi++)
        #pragma unroll
        for (int ni = 0; ni < 4; ni++)
            #pragma unroll
            for (int q = 0; q < 4; q++) acc[mi][ni][q] = 0.f;

    int rowL[4], kqL[4];
    #pragma unroll
    for (int j = 0; j < 4; j++) { int idx = t + j * 256; rowL[j] = idx >> 3; kqL[j] = idx & 7; }

    __syncthreads();   // s_tok/s_bias visible

    float4 pa[4], pb[4];

    auto load_chunk = [&](int ch) {
        #pragma unroll
        for (int j = 0; j < 4; j++) {
            int kabs = Kbase + (ch << 5) + kqL[j] * 4;
            int row = rowL[j];
            const float* ap;
            if (mode == 0) {
                if (kabs < H2)       ap = g_ctx + (size_t)row * H2 + kabs;
                else if (kabs < K1G) ap = emb_table + (size_t)s_tok[row] * EMB + (kabs - H2);
                else                 ap = hidden + (size_t)row * HID + (kabs - K1G);
            } else               ap = h_new + (size_t)row * HID + kabs;
            pa[j] = *(const float4*)ap;
            int rg = nt * 128 + row;
            const float* bp;
            if (mode == 0) bp = (kabs < K1G) ? W_ih + (size_t)rg * K1G + kabs
                                             : W_hh + (size_t)rg * HID + (kabs - K1G);
            else           bp = W_fc + (size_t)rg * HID + kabs;
            pb[j] = *(const float4*)bp;
        }
    };

    auto store_stage = [&](int stg) {
        __nv_bfloat16* Ah = smb + stg * STG_ELEMS;
        __nv_bfloat16* Al = Ah + 5120;
        __nv_bfloat16* Bh = Ah + 10240;
        __nv_bfloat16* Bl = Ah + 15360;
        #pragma unroll
        for (int j = 0; j < 4; j++) {
            int off = rowL[j] * LDS_PAD + kqL[j] * 4;
            float av[4] = { pa[j].x, pa[j].y, pa[j].z, pa[j].w };
            float bv[4] = { pb[j].x, pb[j].y, pb[j].z, pb[j].w };
            __nv_bfloat16 h[4], l[4], bh[4], bl[4];
            #pragma unroll
            for (int c = 0; c < 4; c++) {
                h[c]  = __float2bfloat16(av[c]);
                l[c]  = __float2bfloat16(av[c] - __bfloat162float(h[c]));
                bh[c] = __float2bfloat16(bv[c]);
                bl[c] = __float2bfloat16(bv[c] - __bfloat162float(bh[c]));
            }
            *(__nv_bfloat162*)(Ah + off)     = __halves2bfloat162(h[0],  h[1]);
            *(__nv_bfloat162*)(Ah + off + 2) = __halves2bfloat162(h[2],  h[3]);
            *(__nv_bfloat162*)(Al + off)     = __halves2bfloat162(l[0],  l[1]);
            *(__nv_bfloat162*)(Al + off + 2) = __halves2bfloat162(l[2],  l[3]);
            *(__nv_bfloat162*)(Bh + off)     = __halves2bfloat162(bh[0], bh[1]);
            *(__nv_bfloat162*)(Bh + off + 2) = __halves2bfloat162(bh[2], bh[3]);
            *(__nv_bfloat162*)(Bl + off)     = __halves2bfloat162(bl[0], bl[1]);
            *(__nv_bfloat162*)(Bl + off + 2) = __halves2bfloat162(bl[2], bl[3]);
        }
    };

    int mw = (warp >> 2) * 64, nw = (warp & 3) * 32;

    auto mma_stage = [&](int stg) {
        __nv_bfloat16* Ah = smb + stg * STG_ELEMS;
        __nv_bfloat16* Al = Ah + 5120;
        __nv_bfloat16* Bh = Ah + 10240;
        __nv_bfloat16* Bl = Ah + 15360;
        #pragma unroll
        for (int ks = 0; ks < 2; ks++) {
            uint32_t bh[4][2], bl[4][2];
            int br = nw + (lane & 7);
            int bc = ks * 16 + ((lane >> 3) & 1) * 8;
            #pragma unroll
            for (int ni = 0; ni < 4; ni++) {
                ldm_x2(bh[ni], &Bh[(br + ni * 8) * LDS_PAD + bc]);
                ldm_x2(bl[ni], &Bl[(br + ni * 8) * LDS_PAD + bc]);
            }
            int ar = mw + (lane & 15);
            int ac = ks * 16 + ((lane >> 4) << 3);
            #pragma unroll
            for (int mi = 0; mi < 4; mi++) {
                uint32_t ah[4], al[4];
                ldm_x4(ah, &Ah[(ar + mi * 16) * LDS_PAD + ac]);
                ldm_x4(al, &Al[(ar + mi * 16) * LDS_PAD + ac]);
                #pragma unroll
                for (int ni = 0; ni < 4; ni++) {
                    mma_bf16(acc[mi][ni], ah, bh[ni]);
                    mma_bf16(acc[mi][ni], al, bh[ni]);
                    mma_bf16(acc[mi][ni], ah, bl[ni]);
                }
            }
        }
    };

    // prologue
    load_chunk(0);
    store_stage(0);
    __syncthreads();

    for (int ch = 0; ch < NC; ++ch) {
        int cur = ch & 1;
        if (ch + 1 < NC) load_chunk(ch + 1);   // LDGs fly during mma
        mma_stage(cur);
        if (ch + 1 < NC) store_stage(cur ^ 1);
        __syncthreads();
    }

    // epilogue: direct register stores
    int r0 = mw + (lane >> 2);
    int cb = nw + (lane & 3) * 2;
    if (mode == 0) {
        float* Cp = g_gates_part + (size_t)split * BATCH * NG;
        #pragma unroll
        for (int mi = 0; mi < 4; mi++)
            #pragma unroll
            for (int ni = 0; ni < 4; ni++) {
                int ng0 = nt * 128 + cb + ni * 8;
                int rA  = r0 + mi * 16;
                Cp[(size_t)rA * NG + ng0]           = acc[mi][ni][0];
                Cp[(size_t)rA * NG + ng0 + 1]       = acc[mi][ni][1];
                Cp[(size_t)(rA + 8) * NG + ng0]     = acc[mi][ni][2];
                Cp[(size_t)(rA + 8) * NG + ng0 + 1] = acc[mi][ni][3];
            }
    } else {
        #pragma unroll
        for (int mi = 0; mi < 4; mi++)
            #pragma unroll
            for (int ni = 0; ni < 4; ni++) {
                int c0 = cb + ni * 8;
                int ng0 = nt * 128 + c0;
                int rA  = r0 + mi * 16;
                float b0 = s_bias[c0], b1 = s_bias[c0 + 1];
                pred[(size_t)rA * VOCAB + ng0]           = acc[mi][ni][0] + b0;
                pred[(size_t)rA * VOCAB + ng0 + 1]       = acc[mi][ni][1] + b1;
                pred[(size_t)(rA + 8) * VOCAB + ng0]     = acc[mi][ni][2] + b0;
                pred[(size_t)(rA + 8) * VOCAB + ng0 + 1] = acc[mi][ni][3] + b1;
            }
    }
}

// ===========================================================================
// LSTM pointwise: sum split-K gate partials + biases -> h_new, c_new
// ===========================================================================
__device__ __forceinline__ float sigmf(float v) { return 1.f / (1.f + __expf(-v)); }
__device__ __forceinline__ float tanhfast(float v) { return 1.f - 2.f / (1.f + __expf(2.f * v)); }

__global__ __launch_bounds__(256) void lstm_kernel(
    const float* __restrict__ b_ih, const float* __restrict__ b_hh,
    const float* __restrict__ cell, float* __restrict__ h_out, float* __restrict__ c_out)
{
    int idx = blockIdx.x * 256 + threadIdx.x;
    int b = idx >> 10, j = idx & 1023;
    const float* g = g_gates_part + (size_t)b * NG;
    float gs[4];
    #pragma unroll
    for (int gi = 0; gi < 4; gi++) {
        int col = gi * HID + j;
        float v = b_ih[col] + b_hh[col];
        #pragma unroll
        for (int y = 0; y < GSPLIT; y++) v += g[(size_t)y * BATCH * NG + col];
        gs[gi] = v;
    }
    float ig = sigmf(gs[0]), fg = sigmf(gs[1]);
    float gg = tanhfast(gs[2]), og = sigmf(gs[3]);
    float c = fg * cell[idx] + ig * gg;
    c_out[idx] = c;
    h_out[idx] = og * tanhfast(c);
}

// ===========================================================================
extern "C" void kernel_launch(void* const* d_in, const int* in_sizes, int n_in,
                              void* d_out, int out_size)
{
    const int*   x      = (const int*)d_in[0];
    const float* enc    = (const float*)d_in[1];
    const float* hidden = (const float*)d_in[2];
    const float* cell   = (const float*)d_in[3];
    const float* emb    = (const float*)d_in[4];
    const float* W_e    = (const float*)d_in[5];
    const float* b_e    = (const float*)d_in[6];
    const float* W_ih   = (const float*)d_in[7];
    const float* W_hh   = (const float*)d_in[8];
    const float* b_ih   = (const float*)d_in[9];
    const float* b_hh   = (const float*)d_in[10];
    const float* W_fc   = (const float*)d_in[11];
    const float* b_fc   = (const float*)d_in[12];

    float* out   = (float*)d_out;
    float* h_out = out + (size_t)BATCH * VOCAB;
    float* c_out = h_out + BATCH * HID;

    static bool attr_set = false;
    if (!attr_set) {
        cudaFuncSetAttribute(gemm_kernel, cudaFuncAttributeMaxDynamicSharedMemorySize,
                             GEMM_SMEM);
        attr_set = true;
    }

    attn_kernel<<<BATCH, 256>>>(enc, hidden, W_e, b_e);
    gemm_kernel<<<dim3(NG / 128, GSPLIT), 256, GEMM_SMEM>>>(
        0, x, emb, hidden, W_ih, W_hh, W_fc, b_fc, h_out, out);
    lstm_kernel<<<(BATCH * HID) / 256, 256>>>(b_ih, b_hh, cell, h_out, c_out);
    gemm_kernel<<<dim3(VOCAB / 128, 1), 256, GEMM_SMEM>>>(
        1, x, emb, hidden, W_ih, W_hh, W_fc, b_fc, h_out, out);
}

// round 5
// speedup vs baseline: 1.8059x; 1.5536x over previous
#include <cuda_runtime.h>
#include <cuda_fp16.h>
#include <cstdint>

#define BATCH 128
#define SEQ   512
#define HID   1024
#define H2    2048
#define EMB   512
#define VOCAB 32000
#define KG    3584          /* 2048 ctx + 512 emb + 1024 hidden */
#define NG    4096
#define K1G   (H2 + EMB)    /* 2560 = W_ih K extent */
#define GSPLIT 4            /* split-K for gate GEMM */
#define PAD   40            /* 80B fp16 row stride -> conflict-free ldmatrix */
#define STG_ELEMS (2 * 128 * PAD)           /* Ah|Bh per stage (fp16) */
#define GEMM_SMEM (2 * STG_ELEMS * (int)sizeof(__half))   /* 40KB */

__device__ __half g_act16[BATCH * KG];      // fp16 [ctx | emb | hidden]
__device__ __half g_h16[BATCH * HID];       // fp16 h_new
__device__ float  g_gates_part[GSPLIT * BATCH * NG];

// ===========================================================================
// attention: 1 CTA / batch elem, one streaming pass, no max-shift
// (energies relu-bounded -> exp safe). Two s-rows in flight (MLP ~32),
// W_e read from smem inside the dot (no register copy -> no spills).
// Writes fp16 [ctx | emb | hidden] row for the gate GEMM.
// ===========================================================================
__device__ __forceinline__ void attn_step(
    const float4* __restrict__ w2v4, int lane, const float4 v[16],
    float hb, float& Zw, float4 acc[16])
{
    float pr = 0.f;
    #pragma unroll
    for (int i = 0; i < 16; i++) {
        float4 w = w2v4[lane + 32 * i];     // LDS.128, conflict-free
        pr += v[i].x * w.x + v[i].y * w.y + v[i].z * w.z + v[i].w * w.w;
    }
    #pragma unroll
    for (int o = 16; o > 0; o >>= 1) pr += __shfl_xor_sync(0xffffffffu, pr, o);
    float wg = __expf(fmaxf(pr + hb, 0.f));
    Zw += wg;
    #pragma unroll
    for (int i = 0; i < 16; i++) {
        acc[i].x += wg * v[i].x; acc[i].y += wg * v[i].y;
        acc[i].z += wg * v[i].z; acc[i].w += wg * v[i].w;
    }
}

__global__ __launch_bounds__(256) void attn_kernel(
    const float* __restrict__ enc, const float* __restrict__ hidden,
    const float* __restrict__ W_e, const float* __restrict__ b_e,
    const int* __restrict__ x, const float* __restrict__ emb_table)
{
    __shared__ float s_w2[H2], s_acc[H2];
    __shared__ float s_red[8], s_z[8];
    __shared__ float s_hb, s_invZ;

    int b = blockIdx.x, t = threadIdx.x;
    int warp = t >> 5, lane = t & 31;

    for (int j = t; j < H2; j += 256) { s_w2[j] = W_e[HID + j]; s_acc[j] = 0.f; }

    float p = 0.f;
    for (int j = t; j < HID; j += 256) p += hidden[b * HID + j] * W_e[j];
    #pragma unroll
    for (int o = 16; o > 0; o >>= 1) p += __shfl_xor_sync(0xffffffffu, p, o);
    if (lane == 0) s_red[warp] = p;
    __syncthreads();
    if (t == 0) {
        float s = 0.f;
        #pragma unroll
        for (int i = 0; i < 8; i++) s += s_red[i];
        s_hb = s + b_e[0];
    }
    __syncthreads();
    float hb = s_hb;

    const float4* w2v4 = (const float4*)s_w2;

    float4 acc[16];
    #pragma unroll
    for (int i = 0; i < 16; i++) acc[i] = make_float4(0.f, 0.f, 0.f, 0.f);
    float Zw = 0.f;

    float4 va[16], vb[16];
    {
        const float4* row = (const float4*)(enc + ((size_t)warp * BATCH + b) * H2);
        #pragma unroll
        for (int i = 0; i < 16; i++) va[i] = row[lane + 32 * i];
    }

    for (int s = warp; s < SEQ; s += 16) {
        {   // prefetch s+8 while processing s
            const float4* row = (const float4*)(enc + ((size_t)(s + 8) * BATCH + b) * H2);
            #pragma unroll
            for (int i = 0; i < 16; i++) vb[i] = row[lane + 32 * i];
        }
        attn_step(w2v4, lane, va, hb, Zw, acc);
        if (s + 16 < SEQ) {   // prefetch s+16 while processing s+8
            const float4* row = (const float4*)(enc + ((size_t)(s + 16) * BATCH + b) * H2);
            #pragma unroll
            for (int i = 0; i < 16; i++) va[i] = row[lane + 32 * i];
        }
        attn_step(w2v4, lane, vb, hb, Zw, acc);
    }

    #pragma unroll
    for (int i = 0; i < 16; i++) {
        int c = 4 * (lane + 32 * i);
        atomicAdd(&s_acc[c + 0], acc[i].x);
        atomicAdd(&s_acc[c + 1], acc[i].y);
        atomicAdd(&s_acc[c + 2], acc[i].z);
        atomicAdd(&s_acc[c + 3], acc[i].w);
    }
    if (lane == 0) s_z[warp] = Zw;
    __syncthreads();
    if (t == 0) {
        float z = 0.f;
        #pragma unroll
        for (int i = 0; i < 8; i++) z += s_z[i];
        s_invZ = 1.f / z;
    }
    __syncthreads();
    float iz = s_invZ;

    __half* dst = g_act16 + (size_t)b * KG;
    for (int j = t; j < H2; j += 256) dst[j] = __float2half(s_acc[j] * iz);
    int tok = x[b];
    for (int j = t; j < EMB; j += 256)
        dst[H2 + j] = __float2half(emb_table[(size_t)tok * EMB + j]);
    for (int j = t; j < HID; j += 256)
        dst[K1G + j] = __float2half(hidden[b * HID + j]);
}

// ===========================================================================
// fp16 GEMM (mma.sync m16n8k16), double-buffered smem, 2 CTAs/SM:
//   C[128, 128-tile] = A[128,K] @ B[Ntile,K]^T
// A pre-converted fp16 (g_act16 / g_h16); B = fp32 weights cvt on the fly.
// mode 0: gates (B = W_ih|W_hh piecewise, K split GSPLIT ways -> partials)
// mode 1: fc    (B = W_fc, C = pred + bias)
// ===========================================================================
__device__ __forceinline__ void ldm_x4(uint32_t* r, const __half* p) {
    uint32_t a = (uint32_t)__cvta_generic_to_shared(p);
    asm volatile("ldmatrix.sync.aligned.m8n8.x4.shared.b16 {%0,%1,%2,%3}, [%4];\n"
                 : "=r"(r[0]), "=r"(r[1]), "=r"(r[2]), "=r"(r[3]) : "r"(a));
}
__device__ __forceinline__ void ldm_x2(uint32_t* r, const __half* p) {
    uint32_t a = (uint32_t)__cvta_generic_to_shared(p);
    asm volatile("ldmatrix.sync.aligned.m8n8.x2.shared.b16 {%0,%1}, [%2];\n"
                 : "=r"(r[0]), "=r"(r[1]) : "r"(a));
}
__device__ __forceinline__ void mma_f16(float* d, const uint32_t* a, const uint32_t* b) {
    asm volatile("mma.sync.aligned.m16n8k16.row.col.f32.f16.f16.f32 "
                 "{%0,%1,%2,%3}, {%4,%5,%6,%7}, {%8,%9}, {%0,%1,%2,%3};\n"
                 : "+f"(d[0]), "+f"(d[1]), "+f"(d[2]), "+f"(d[3])
                 : "r"(a[0]), "r"(a[1]), "r"(a[2]), "r"(a[3]), "r"(b[0]), "r"(b[1]));
}
__device__ __forceinline__ uint32_t pk(float a, float b) {
    __half2 h = __floats2half2_rn(a, b);
    return *reinterpret_cast<uint32_t*>(&h);
}

extern __shared__ __half smb[];

__global__ __launch_bounds__(256, 2) void gemm_kernel(
    int mode,
    const float* __restrict__ W_ih, const float* __restrict__ W_hh,
    const float* __restrict__ W_fc, const float* __restrict__ b_fc,
    float* __restrict__ pred)
{
    __shared__ float s_bias[128];

    int t = threadIdx.x, warp = t >> 5, lane = t & 31;
    int nt = blockIdx.x, split = blockIdx.y;

    const __half* Aact = (mode == 0) ? g_act16 : g_h16;
    int lda   = (mode == 0) ? KG : HID;
    int Kbase = (mode == 0) ? split * (KG / GSPLIT) : 0;
    int NC    = (mode == 0) ? (KG / GSPLIT) >> 5 : HID >> 5;

    if (mode == 1 && t < 128) s_bias[t] = b_fc[nt * 128 + t];

    float acc[4][4][4];
    #pragma unroll
    for (int mi = 0; mi < 4; mi++)
        #pragma unroll
        for (int ni = 0; ni < 4; ni++)
            #pragma unroll
            for (int q = 0; q < 4; q++) acc[mi][ni][q] = 0.f;

    // 512 slots (128 rows x 4 groups-of-8); each thread owns 2
    int rw[2], gp[2];
    #pragma unroll
    for (int j = 0; j < 2; j++) { int id = t + j * 256; rw[j] = id >> 2; gp[j] = id & 3; }

    uint4  aS[2];
    float4 bS[2][2];

    auto load_chunk = [&](int ch) {
        #pragma unroll
        for (int j = 0; j < 2; j++) {
            int k = Kbase + (ch << 5) + gp[j] * 8;
            aS[j] = *(const uint4*)(Aact + (size_t)rw[j] * lda + k);
            int rg = nt * 128 + rw[j];
            const float* bp;
            if (mode == 0) bp = (k < K1G) ? W_ih + (size_t)rg * K1G + k
                                          : W_hh + (size_t)rg * HID + (k - K1G);
            else           bp = W_fc + (size_t)rg * HID + k;
            bS[j][0] = ((const float4*)bp)[0];
            bS[j][1] = ((const float4*)bp)[1];
        }
    };

    auto store_stage = [&](int stg) {
        __half* Ah = smb + stg * STG_ELEMS;
        __half* Bh = Ah + 128 * PAD;
        #pragma unroll
        for (int j = 0; j < 2; j++) {
            int off = rw[j] * PAD + gp[j] * 8;
            *(uint4*)(Ah + off) = aS[j];
            uint4 bp16 = make_uint4(pk(bS[j][0].x, bS[j][0].y), pk(bS[j][0].z, bS[j][0].w),
                                    pk(bS[j][1].x, bS[j][1].y), pk(bS[j][1].z, bS[j][1].w));
            *(uint4*)(Bh + off) = bp16;
        }
    };

    int mw = (warp >> 2) * 64, nw = (warp & 3) * 32;

    auto mma_stage = [&](int stg) {
        __half* Ah = smb + stg * STG_ELEMS;
        __half* Bh = Ah + 128 * PAD;
        #pragma unroll
        for (int ks = 0; ks < 2; ks++) {
            uint32_t bh[4][2];
            int br = nw + (lane & 7);
            int bc = ks * 16 + ((lane >> 3) & 1) * 8;
            #pragma unroll
            for (int ni = 0; ni < 4; ni++)
                ldm_x2(bh[ni], &Bh[(br + ni * 8) * PAD + bc]);
            int ar = mw + (lane & 15);
            int ac = ks * 16 + ((lane >> 4) << 3);
            #pragma unroll
            for (int mi = 0; mi < 4; mi++) {
                uint32_t ah[4];
                ldm_x4(ah, &Ah[(ar + mi * 16) * PAD + ac]);
                #pragma unroll
                for (int ni = 0; ni < 4; ni++)
                    mma_f16(acc[mi][ni], ah, bh[ni]);
            }
        }
    };

    load_chunk(0);
    store_stage(0);
    __syncthreads();

    for (int ch = 0; ch < NC; ++ch) {
        int cur = ch & 1;
        if (ch + 1 < NC) load_chunk(ch + 1);   // LDGs in flight during mma
        mma_stage(cur);
        if (ch + 1 < NC) store_stage(cur ^ 1);
        __syncthreads();
    }

    // epilogue
    int r0 = mw + (lane >> 2);
    int cb = nw + (lane & 3) * 2;
    if (mode == 0) {
        float* Cp = g_gates_part + (size_t)split * BATCH * NG;
        #pragma unroll
        for (int mi = 0; mi < 4; mi++)
            #pragma unroll
            for (int ni = 0; ni < 4; ni++) {
                int ng0 = nt * 128 + cb + ni * 8;
                int rA  = r0 + mi * 16;
                Cp[(size_t)rA * NG + ng0]           = acc[mi][ni][0];
                Cp[(size_t)rA * NG + ng0 + 1]       = acc[mi][ni][1];
                Cp[(size_t)(rA + 8) * NG + ng0]     = acc[mi][ni][2];
                Cp[(size_t)(rA + 8) * NG + ng0 + 1] = acc[mi][ni][3];
            }
    } else {
        #pragma unroll
        for (int mi = 0; mi < 4; mi++)
            #pragma unroll
            for (int ni = 0; ni < 4; ni++) {
                int c0 = cb + ni * 8;
                int ng0 = nt * 128 + c0;
                int rA  = r0 + mi * 16;
                float b0 = s_bias[c0], b1 = s_bias[c0 + 1];
                pred[(size_t)rA * VOCAB + ng0]           = acc[mi][ni][0] + b0;
                pred[(size_t)rA * VOCAB + ng0 + 1]       = acc[mi][ni][1] + b1;
                pred[(size_t)(rA + 8) * VOCAB + ng0]     = acc[mi][ni][2] + b0;
                pred[(size_t)(rA + 8) * VOCAB + ng0 + 1] = acc[mi][ni][3] + b1;
            }
    }
}

// ===========================================================================
// LSTM pointwise: sum split-K gate partials + biases -> h_new (fp32 + fp16), c_new
// ===========================================================================
__device__ __forceinline__ float sigmf(float v) { return 1.f / (1.f + __expf(-v)); }
__device__ __forceinline__ float tanhfast(float v) { return 1.f - 2.f / (1.f + __expf(2.f * v)); }

__global__ __launch_bounds__(256) void lstm_kernel(
    const float* __restrict__ b_ih, const float* __restrict__ b_hh,
    const float* __restrict__ cell, float* __restrict__ h_out, float* __restrict__ c_out)
{
    int idx = blockIdx.x * 256 + threadIdx.x;
    int b = idx >> 10, j = idx & 1023;
    const float* g = g_gates_part + (size_t)b * NG;
    float gs[4];
    #pragma unroll
    for (int gi = 0; gi < 4; gi++) {
        int col = gi * HID + j;
        float v = b_ih[col] + b_hh[col];
        #pragma unroll
        for (int y = 0; y < GSPLIT; y++) v += g[(size_t)y * BATCH * NG + col];
        gs[gi] = v;
    }
    float ig = sigmf(gs[0]), fg = sigmf(gs[1]);
    float gg = tanhfast(gs[2]), og = sigmf(gs[3]);
    float c = fg * cell[idx] + ig * gg;
    float h = og * tanhfast(c);
    c_out[idx] = c;
    h_out[idx] = h;
    g_h16[idx] = __float2half(h);
}

// ===========================================================================
extern "C" void kernel_launch(void* const* d_in, const int* in_sizes, int n_in,
                              void* d_out, int out_size)
{
    const int*   x      = (const int*)d_in[0];
    const float* enc    = (const float*)d_in[1];
    const float* hidden = (const float*)d_in[2];
    const float* cell   = (const float*)d_in[3];
    const float* emb    = (const float*)d_in[4];
    const float* W_e    = (const float*)d_in[5];
    const float* b_e    = (const float*)d_in[6];
    const float* W_ih   = (const float*)d_in[7];
    const float* W_hh   = (const float*)d_in[8];
    const float* b_ih   = (const float*)d_in[9];
    const float* b_hh   = (const float*)d_in[10];
    const float* W_fc   = (const float*)d_in[11];
    const float* b_fc   = (const float*)d_in[12];

    float* out   = (float*)d_out;
    float* h_out = out + (size_t)BATCH * VOCAB;
    float* c_out = h_out + BATCH * HID;

    attn_kernel<<<BATCH, 256>>>(enc, hidden, W_e, b_e, x, emb);
    gemm_kernel<<<dim3(NG / 128, GSPLIT), 256, GEMM_SMEM>>>(
        0, W_ih, W_hh, W_fc, b_fc, out);
    lstm_kernel<<<(BATCH * HID) / 256, 256>>>(b_ih, b_hh, cell, h_out, c_out);
    gemm_kernel<<<dim3(VOCAB / 128, 1), 256, GEMM_SMEM>>>(
        1, W_ih, W_hh, W_fc, b_fc, out);
}